// round 1
// baseline (speedup 1.0000x reference)
#include <cuda_runtime.h>
#include <math_constants.h>

// Problem: B=32, S=2048, F=512. Output = one-hot(argmax over F of logits+gumbel).
// (See analysis: the straight-through mask is exactly one-hot in forward numerics,
//  and the top-K-smallest-zeroing only touches entries that are already 0.)

static constexpr int Bc = 32;
static constexpr int Sc = 2048;
static constexpr int Fc = 512;
static constexpr int ROWS = Bc * Sc;          // 65536 rows
static constexpr int F4  = Fc / 4;            // 128 float4 per row

__global__ __launch_bounds__(256)
void onehot_argmax_kernel(const float4* __restrict__ logits,
                          const float4* __restrict__ gumbel,
                          float4* __restrict__ out) {
    const int warp = (blockIdx.x * blockDim.x + threadIdx.x) >> 5;
    const int lane = threadIdx.x & 31;
    if (warp >= ROWS) return;

    const size_t base = (size_t)warp * F4;

    float best = -CUDART_INF_F;
    int   bidx = 0;

    // Each lane handles 4 float4s: positions c*32 + lane (c = 0..3).
    // Within a lane indices are strictly increasing, so "strict >" gives
    // first-index tie-break per lane; cross-lane tie-break done in reduction.
    #pragma unroll
    for (int c = 0; c < 4; c++) {
        const int p = c * 32 + lane;
        const float4 a = logits[base + p];
        const float4 g = gumbel[base + p];
        const float s0 = a.x + g.x;
        const float s1 = a.y + g.y;
        const float s2 = a.z + g.z;
        const float s3 = a.w + g.w;
        const int e = p * 4;
        if (s0 > best) { best = s0; bidx = e;     }
        if (s1 > best) { best = s1; bidx = e + 1; }
        if (s2 > best) { best = s2; bidx = e + 2; }
        if (s3 > best) { best = s3; bidx = e + 3; }
    }

    // Butterfly reduction: max by value, lowest index on ties (matches jnp.argmax).
    // The combine op is associative+commutative (lexicographic max on (val, -idx)),
    // so the xor-butterfly leaves ALL lanes holding the row argmax — no broadcast
    // or __syncwarp needed before the store phase.
    #pragma unroll
    for (int off = 16; off; off >>= 1) {
        const float ov = __shfl_xor_sync(0xffffffffu, best, off);
        const int   oi = __shfl_xor_sync(0xffffffffu, bidx, off);
        if (ov > best || (ov == best && oi < bidx)) { best = ov; bidx = oi; }
    }

    // Write the one-hot row: each lane composes its float4s locally (no RMW race).
    #pragma unroll
    for (int c = 0; c < 4; c++) {
        const int p = c * 32 + lane;
        const int e = p * 4;
        float4 o;
        o.x = (e     == bidx) ? 1.0f : 0.0f;
        o.y = (e + 1 == bidx) ? 1.0f : 0.0f;
        o.z = (e + 2 == bidx) ? 1.0f : 0.0f;
        o.w = (e + 3 == bidx) ? 1.0f : 0.0f;
        out[base + p] = o;
    }
}

extern "C" void kernel_launch(void* const* d_in, const int* in_sizes, int n_in,
                              void* d_out, int out_size) {
    const float4* logits = (const float4*)d_in[0];
    const float4* gumbel = (const float4*)d_in[1];
    float4* out = (float4*)d_out;

    // One warp per row; 8 warps per 256-thread block -> 8192 blocks.
    const int threads = 256;
    const int warps_per_block = threads / 32;
    const int blocks = (ROWS + warps_per_block - 1) / warps_per_block;
    onehot_argmax_kernel<<<blocks, threads>>>(logits, gumbel, out);
}